// round 1
// baseline (speedup 1.0000x reference)
#include <cuda_runtime.h>

// Problem constants
#define BB     4
#define NSEQ   2048
#define EE     1600
#define RR     448
#define HH     512
#define NHEAD  4
#define DHEAD  128
#define PP     2
#define FFD    2048
#define MTOK   (BB*NSEQ)   // 8192 token rows

// -------- scratch (device globals; no allocation allowed) --------
__device__ float g_x[(size_t)BB*NSEQ*HH];
__device__ float g_q[(size_t)BB*NSEQ*HH];
__device__ float g_k[(size_t)BB*NSEQ*HH];
__device__ float g_v[(size_t)BB*NSEQ*HH];
__device__ float g_t[(size_t)BB*NSEQ*HH];
__device__ float g_f[(size_t)BB*NSEQ*FFD];
__device__ float g_s[(size_t)BB*NHEAD*NSEQ*NSEQ];   // 268 MB scores

// -------- build x = concat(vents, renc_w[rels]) --------
__global__ void k_build_x(const float* __restrict__ vents,
                          const float* __restrict__ renc,
                          const int*   __restrict__ rels) {
    int idx = blockIdx.x * blockDim.x + threadIdx.x;   // over B*N*(H/4)
    const int H4 = HH / 4;
    if (idx >= BB * NSEQ * H4) return;
    int hv = idx % H4;
    int n  = (idx / H4) % NSEQ;
    int b  = idx / (H4 * NSEQ);
    float4 val;
    if (n < EE) {
        val = ((const float4*)vents)[(size_t)(b * EE + n) * H4 + hv];
    } else {
        int r = rels[b * RR + (n - EE)];
        val = ((const float4*)renc)[(size_t)r * H4 + hv];
    }
    ((float4*)g_x)[idx] = val;
}

// -------- generic sgemm: C[M,N] = A[M,K] @ W[K,N] (+bias)(+prelu) --------
// block tile 128x128, K tile 8, 256 threads, 8x8 per thread
template<int EPI>   // 0: none, 1: +bias, 2: +bias +prelu(alpha per col)
__global__ __launch_bounds__(256)
void k_sgemm(const float* __restrict__ A, int lda,
             const float* __restrict__ W, int ldw,
             float* __restrict__ C, int ldc, int K,
             const float* __restrict__ bias,
             const float* __restrict__ alpha) {
    __shared__ float As[8][128];
    __shared__ float Ws[8][128];
    const int tid  = threadIdx.x;
    const int tx   = tid & 15, ty = tid >> 4;
    const int arow = tid >> 1, acol = (tid & 1) << 2;
    const int wrow = tid >> 5, wcol = (tid & 31) << 2;
    const float* Ab = A + (size_t)(blockIdx.y * 128) * lda;
    const float* Wb = W + blockIdx.x * 128;

    float acc[8][8];
#pragma unroll
    for (int i = 0; i < 8; i++)
#pragma unroll
        for (int j = 0; j < 8; j++) acc[i][j] = 0.f;

    for (int k0 = 0; k0 < K; k0 += 8) {
        float4 av = *(const float4*)(Ab + (size_t)arow * lda + (k0 + acol));
        float4 wv = *(const float4*)(Wb + (size_t)(k0 + wrow) * ldw + wcol);
        As[acol + 0][arow] = av.x; As[acol + 1][arow] = av.y;
        As[acol + 2][arow] = av.z; As[acol + 3][arow] = av.w;
        *(float4*)&Ws[wrow][wcol] = wv;
        __syncthreads();
#pragma unroll
        for (int kk = 0; kk < 8; kk++) {
            float4 a0 = *(const float4*)&As[kk][ty * 8];
            float4 a1 = *(const float4*)&As[kk][ty * 8 + 4];
            float4 b0 = *(const float4*)&Ws[kk][tx * 8];
            float4 b1 = *(const float4*)&Ws[kk][tx * 8 + 4];
            float ar[8] = {a0.x, a0.y, a0.z, a0.w, a1.x, a1.y, a1.z, a1.w};
            float br[8] = {b0.x, b0.y, b0.z, b0.w, b1.x, b1.y, b1.z, b1.w};
#pragma unroll
            for (int i = 0; i < 8; i++)
#pragma unroll
                for (int j = 0; j < 8; j++) acc[i][j] += ar[i] * br[j];
        }
        __syncthreads();
    }

    const int row0 = blockIdx.y * 128 + ty * 8;
    const int col0 = blockIdx.x * 128 + tx * 8;
    float bb[8], aa[8];
#pragma unroll
    for (int j = 0; j < 8; j++) {
        bb[j] = (EPI >= 1) ? bias[col0 + j] : 0.f;
        aa[j] = (EPI == 2) ? alpha[col0 + j] : 0.f;
    }
#pragma unroll
    for (int i = 0; i < 8; i++) {
        float o[8];
#pragma unroll
        for (int j = 0; j < 8; j++) {
            float v = acc[i][j];
            if (EPI >= 1) v += bb[j];
            if (EPI == 2) v = (v >= 0.f) ? v : aa[j] * v;
            o[j] = v;
        }
        float* cp = C + (size_t)(row0 + i) * ldc + col0;
        *(float4*)cp       = make_float4(o[0], o[1], o[2], o[3]);
        *(float4*)(cp + 4) = make_float4(o[4], o[5], o[6], o[7]);
    }
}

// -------- attention scores: S = (Q K^T)/sqrt(DH), masked by adj --------
__global__ __launch_bounds__(256)
void k_scores(const int* __restrict__ adjs) {
    const int z = blockIdx.z, b = z >> 2, h = z & 3;
    const float* Q  = g_q + (size_t)b * NSEQ * HH + h * DHEAD;
    const float* Km = g_k + (size_t)b * NSEQ * HH + h * DHEAD;
    __shared__ float Qs[8][128];
    __shared__ float Ks[8][128];
    const int tid  = threadIdx.x;
    const int tx   = tid & 15, ty = tid >> 4;
    const int arow = tid >> 1, acol = (tid & 1) << 2;
    const int q0 = blockIdx.y * 128, k0 = blockIdx.x * 128;

    float acc[8][8];
#pragma unroll
    for (int i = 0; i < 8; i++)
#pragma unroll
        for (int j = 0; j < 8; j++) acc[i][j] = 0.f;

    for (int kc = 0; kc < DHEAD; kc += 8) {
        float4 qv = *(const float4*)(Q  + (size_t)(q0 + arow) * HH + kc + acol);
        float4 kv = *(const float4*)(Km + (size_t)(k0 + arow) * HH + kc + acol);
        Qs[acol + 0][arow] = qv.x; Qs[acol + 1][arow] = qv.y;
        Qs[acol + 2][arow] = qv.z; Qs[acol + 3][arow] = qv.w;
        Ks[acol + 0][arow] = kv.x; Ks[acol + 1][arow] = kv.y;
        Ks[acol + 2][arow] = kv.z; Ks[acol + 3][arow] = kv.w;
        __syncthreads();
#pragma unroll
        for (int kk = 0; kk < 8; kk++) {
            float4 a0 = *(const float4*)&Qs[kk][ty * 8];
            float4 a1 = *(const float4*)&Qs[kk][ty * 8 + 4];
            float4 b0 = *(const float4*)&Ks[kk][tx * 8];
            float4 b1 = *(const float4*)&Ks[kk][tx * 8 + 4];
            float ar[8] = {a0.x, a0.y, a0.z, a0.w, a1.x, a1.y, a1.z, a1.w};
            float br[8] = {b0.x, b0.y, b0.z, b0.w, b1.x, b1.y, b1.z, b1.w};
#pragma unroll
            for (int i = 0; i < 8; i++)
#pragma unroll
                for (int j = 0; j < 8; j++) acc[i][j] += ar[i] * br[j];
        }
        __syncthreads();
    }

    const float rs = 0.08838834764831845f;   // 1/sqrt(128)
    float* S = g_s + (size_t)z * NSEQ * NSEQ;
    const int* adj = adjs + (size_t)b * NSEQ * NSEQ;
#pragma unroll
    for (int i = 0; i < 8; i++) {
        int row = q0 + ty * 8 + i;
        float o[8];
#pragma unroll
        for (int j = 0; j < 8; j++) {
            int col = k0 + tx * 8 + j;
            float v = acc[i][j] * rs;
            if (adj[(size_t)row * NSEQ + col] == 0) v = -1e9f;
            o[j] = v;
        }
        float* sp = S + (size_t)row * NSEQ + k0 + tx * 8;
        *(float4*)sp       = make_float4(o[0], o[1], o[2], o[3]);
        *(float4*)(sp + 4) = make_float4(o[4], o[5], o[6], o[7]);
    }
}

// -------- softmax over rows of g_s (register-resident, 1R + 1W) --------
__global__ __launch_bounds__(256)
void k_softmax() {
    float* p = g_s + (size_t)blockIdx.x * NSEQ;
    const int tid = threadIdx.x;
    float4 v0 = ((const float4*)p)[tid];
    float4 v1 = ((const float4*)p)[tid + 256];
    float m = fmaxf(fmaxf(fmaxf(v0.x, v0.y), fmaxf(v0.z, v0.w)),
                    fmaxf(fmaxf(v1.x, v1.y), fmaxf(v1.z, v1.w)));
    __shared__ float red[8];
#pragma unroll
    for (int o = 16; o; o >>= 1) m = fmaxf(m, __shfl_xor_sync(~0u, m, o));
    if ((tid & 31) == 0) red[tid >> 5] = m;
    __syncthreads();
    float mAll = red[0];
#pragma unroll
    for (int i = 1; i < 8; i++) mAll = fmaxf(mAll, red[i]);

    v0.x = expf(v0.x - mAll); v0.y = expf(v0.y - mAll);
    v0.z = expf(v0.z - mAll); v0.w = expf(v0.w - mAll);
    v1.x = expf(v1.x - mAll); v1.y = expf(v1.y - mAll);
    v1.z = expf(v1.z - mAll); v1.w = expf(v1.w - mAll);
    float s = v0.x + v0.y + v0.z + v0.w + v1.x + v1.y + v1.z + v1.w;
    __syncthreads();
#pragma unroll
    for (int o = 16; o; o >>= 1) s += __shfl_xor_sync(~0u, s, o);
    if ((tid & 31) == 0) red[tid >> 5] = s;
    __syncthreads();
    float sAll = red[0];
#pragma unroll
    for (int i = 1; i < 8; i++) sAll += red[i];
    float inv = 1.f / sAll;

    v0.x *= inv; v0.y *= inv; v0.z *= inv; v0.w *= inv;
    v1.x *= inv; v1.y *= inv; v1.z *= inv; v1.w *= inv;
    ((float4*)p)[tid]       = v0;
    ((float4*)p)[tid + 256] = v1;
}

// -------- O = A @ V per (b,h); writes into g_q[b, :, h*DH .. ] --------
__global__ __launch_bounds__(256)
void k_av() {
    const int z = blockIdx.z, b = z >> 2, h = z & 3;
    const float* A = g_s + (size_t)z * NSEQ * NSEQ;
    const float* V = g_v + (size_t)b * NSEQ * HH + h * DHEAD;
    float* C       = g_q + (size_t)b * NSEQ * HH + h * DHEAD;
    __shared__ float As[8][128];
    __shared__ float Vs[8][128];
    const int tid  = threadIdx.x;
    const int tx   = tid & 15, ty = tid >> 4;
    const int arow = tid >> 1, acol = (tid & 1) << 2;
    const int wrow = tid >> 5, wcol = (tid & 31) << 2;
    const int q0 = blockIdx.y * 128;

    float acc[8][8];
#pragma unroll
    for (int i = 0; i < 8; i++)
#pragma unroll
        for (int j = 0; j < 8; j++) acc[i][j] = 0.f;

    for (int k0 = 0; k0 < NSEQ; k0 += 8) {
        float4 av = *(const float4*)(A + (size_t)(q0 + arow) * NSEQ + k0 + acol);
        float4 vv = *(const float4*)(V + (size_t)(k0 + wrow) * HH + wcol);
        As[acol + 0][arow] = av.x; As[acol + 1][arow] = av.y;
        As[acol + 2][arow] = av.z; As[acol + 3][arow] = av.w;
        *(float4*)&Vs[wrow][wcol] = vv;
        __syncthreads();
#pragma unroll
        for (int kk = 0; kk < 8; kk++) {
            float4 a0 = *(const float4*)&As[kk][ty * 8];
            float4 a1 = *(const float4*)&As[kk][ty * 8 + 4];
            float4 b0 = *(const float4*)&Vs[kk][tx * 8];
            float4 b1 = *(const float4*)&Vs[kk][tx * 8 + 4];
            float ar[8] = {a0.x, a0.y, a0.z, a0.w, a1.x, a1.y, a1.z, a1.w};
            float br[8] = {b0.x, b0.y, b0.z, b0.w, b1.x, b1.y, b1.z, b1.w};
#pragma unroll
            for (int i = 0; i < 8; i++)
#pragma unroll
                for (int j = 0; j < 8; j++) acc[i][j] += ar[i] * br[j];
        }
        __syncthreads();
    }
#pragma unroll
    for (int i = 0; i < 8; i++) {
        float* cp = C + (size_t)(q0 + ty * 8 + i) * HH + tx * 8;
        *(float4*)cp       = make_float4(acc[i][0], acc[i][1], acc[i][2], acc[i][3]);
        *(float4*)(cp + 4) = make_float4(acc[i][4], acc[i][5], acc[i][6], acc[i][7]);
    }
}

// -------- layernorm (optional residual add), warp per row --------
__global__ __launch_bounds__(256)
void k_ln(const float* __restrict__ X, const float* __restrict__ Rres,
          const float* __restrict__ g, const float* __restrict__ bsh,
          float* __restrict__ out) {
    const int row  = blockIdx.x * 8 + (threadIdx.x >> 5);
    const int lane = threadIdx.x & 31;
    const float4* xr = (const float4*)(X + (size_t)row * HH);
    float4 v[4];
    float sum = 0.f, sq = 0.f;
#pragma unroll
    for (int i = 0; i < 4; i++) {
        float4 a = xr[lane + 32 * i];
        if (Rres) {
            float4 r = ((const float4*)(Rres + (size_t)row * HH))[lane + 32 * i];
            a.x += r.x; a.y += r.y; a.z += r.z; a.w += r.w;
        }
        v[i] = a;
        sum += a.x + a.y + a.z + a.w;
        sq  += a.x * a.x + a.y * a.y + a.z * a.z + a.w * a.w;
    }
#pragma unroll
    for (int o = 16; o; o >>= 1) {
        sum += __shfl_xor_sync(~0u, sum, o);
        sq  += __shfl_xor_sync(~0u, sq,  o);
    }
    const float mu   = sum * (1.f / HH);
    const float var  = sq * (1.f / HH) - mu * mu;
    const float rstd = rsqrtf(var + 1e-5f);
    float4* op = (float4*)(out + (size_t)row * HH);
#pragma unroll
    for (int i = 0; i < 4; i++) {
        int c4 = lane + 32 * i;
        float4 gg = ((const float4*)g)[c4];
        float4 bb = ((const float4*)bsh)[c4];
        float4 a = v[i];
        a.x = (a.x - mu) * rstd * gg.x + bb.x;
        a.y = (a.y - mu) * rstd * gg.y + bb.y;
        a.z = (a.z - mu) * rstd * gg.z + bb.z;
        a.w = (a.w - mu) * rstd * gg.w + bb.w;
        op[c4] = a;
    }
}

// -------- output assembly: [glob | gents | emask] --------
__global__ void k_out(float* __restrict__ out) {
    const size_t GENTS = (size_t)BB * NSEQ * HH;
    size_t i = (size_t)blockIdx.x * 256 + threadIdx.x;
    if (i < (size_t)BB * HH) {
        size_t b = i / HH, hc = i % HH;
        out[i] = g_x[b * NSEQ * HH + (size_t)EE * HH + hc];
    }
    if (i < GENTS) out[(size_t)BB * HH + i] = g_x[i];
    if (i < (size_t)BB * NSEQ) out[(size_t)BB * HH + GENTS + i] = 1.0f;
}

extern "C" void kernel_launch(void* const* d_in, const int* in_sizes, int n_in,
                              void* d_out, int out_size) {
    // entlen may or may not be materialized as an input (python int in dict)
    int s = (n_in >= 22) ? 1 : 0;
    const int*   adjs  = (const int*)d_in[0];
    const int*   rels  = (const int*)d_in[1];
    const float* vents = (const float*)d_in[2];
    const float* renc  = (const float*)d_in[3 + s];
    const float* Wq = (const float*)d_in[4 + s];
    const float* Wk = (const float*)d_in[5 + s];
    const float* Wv = (const float*)d_in[6 + s];
    const float* Wo = (const float*)d_in[7 + s];
    const float* W1 = (const float*)d_in[8 + s];
    const float* W2 = (const float*)d_in[9 + s];
    const float* bq = (const float*)d_in[10 + s];
    const float* bk = (const float*)d_in[11 + s];
    const float* bv = (const float*)d_in[12 + s];
    const float* bo = (const float*)d_in[13 + s];
    const float* b1 = (const float*)d_in[14 + s];
    const float* b2 = (const float*)d_in[15 + s];
    const float* ln1g = (const float*)d_in[16 + s];
    const float* ln1b = (const float*)d_in[17 + s];
    const float* ln2g = (const float*)d_in[18 + s];
    const float* ln2b = (const float*)d_in[19 + s];
    const float* pa   = (const float*)d_in[20 + s];

    float *px, *pq, *pk, *pv, *pt, *pf;
    cudaGetSymbolAddress((void**)&px, g_x);
    cudaGetSymbolAddress((void**)&pq, g_q);
    cudaGetSymbolAddress((void**)&pk, g_k);
    cudaGetSymbolAddress((void**)&pv, g_v);
    cudaGetSymbolAddress((void**)&pt, g_t);
    cudaGetSymbolAddress((void**)&pf, g_f);

    k_build_x<<<(BB * NSEQ * (HH / 4) + 255) / 256, 256>>>(vents, renc, rels);

    for (int j = 0; j < PP; j++) {
        const float* Wqj = Wq + (size_t)j * HH * HH;
        const float* Wkj = Wk + (size_t)j * HH * HH;
        const float* Wvj = Wv + (size_t)j * HH * HH;
        const float* Woj = Wo + (size_t)j * HH * HH;
        const float* W1j = W1 + (size_t)j * HH * FFD;
        const float* W2j = W2 + (size_t)j * FFD * HH;

        dim3 gp(HH / 128, MTOK / 128);          // (4, 64)
        k_sgemm<1><<<gp, 256>>>(px, HH, Wqj, HH, pq, HH, HH, bq + j * HH, nullptr);
        k_sgemm<1><<<gp, 256>>>(px, HH, Wkj, HH, pk, HH, HH, bk + j * HH, nullptr);
        k_sgemm<1><<<gp, 256>>>(px, HH, Wvj, HH, pv, HH, HH, bv + j * HH, nullptr);

        dim3 gs(NSEQ / 128, NSEQ / 128, BB * NHEAD);
        k_scores<<<gs, 256>>>(adjs);
        k_softmax<<<BB * NHEAD * NSEQ, 256>>>();
        dim3 ga(1, NSEQ / 128, BB * NHEAD);
        k_av<<<ga, 256>>>();                     // o -> g_q

        k_sgemm<1><<<gp, 256>>>(pq, HH, Woj, HH, pk, HH, HH, bo + j * HH, nullptr);
        k_ln<<<MTOK / 8, 256>>>(pk, nullptr, ln1g + j * HH, ln1b + j * HH, pt);

        dim3 g1(FFD / 128, MTOK / 128);
        k_sgemm<2><<<g1, 256>>>(pt, HH, W1j, FFD, pf, FFD, HH, b1 + j * FFD, pa + j * FFD);
        dim3 g2(HH / 128, MTOK / 128);
        k_sgemm<1><<<g2, 256>>>(pf, FFD, W2j, HH, pk, HH, FFD, b2 + j * HH, nullptr);

        k_ln<<<MTOK / 8, 256>>>(pk, pt, ln2g + j * HH, ln2b + j * HH, px);
    }

    k_out<<<(BB * NSEQ * HH + 255) / 256, 256>>>((float*)d_out);
}

// round 2
// speedup vs baseline: 1.0714x; 1.0714x over previous
#include <cuda_runtime.h>

// Problem constants
#define BB     4
#define NSEQ   2048
#define EE     1600
#define RR     448
#define HH     512
#define NHEAD  4
#define DHEAD  128
#define PP     2
#define FFD    2048
#define MTOK   (BB*NSEQ)   // 8192 token rows

// -------- scratch (device globals; no allocation allowed) --------
__device__ float g_x[(size_t)BB*NSEQ*HH];
__device__ float g_q[(size_t)BB*NSEQ*HH];
__device__ float g_k[(size_t)BB*NSEQ*HH];
__device__ float g_v[(size_t)BB*NSEQ*HH];
__device__ float g_t[(size_t)BB*NSEQ*HH];
__device__ float g_f[(size_t)BB*NSEQ*FFD];
__device__ float g_s[(size_t)BB*NHEAD*NSEQ*NSEQ];   // 268 MB scores

// ---------------- helpers ----------------
__device__ __forceinline__ unsigned f2tf32(float x) {
    unsigned r;
    asm("cvt.rna.tf32.f32 %0, %1;" : "=r"(r) : "f"(x));
    return r;
}

__device__ __forceinline__ void mma_tf32(float* d, const unsigned* a, const unsigned* b) {
    asm volatile("mma.sync.aligned.m16n8k8.row.col.f32.tf32.tf32.f32 "
                 "{%0,%1,%2,%3}, {%4,%5,%6,%7}, {%8,%9}, {%0,%1,%2,%3};"
                 : "+f"(d[0]), "+f"(d[1]), "+f"(d[2]), "+f"(d[3])
                 : "r"(a[0]), "r"(a[1]), "r"(a[2]), "r"(a[3]),
                   "r"(b[0]), "r"(b[1]));
}

// -------- build x = concat(vents, renc_w[rels]) --------
__global__ void k_build_x(const float* __restrict__ vents,
                          const float* __restrict__ renc,
                          const int*   __restrict__ rels) {
    int idx = blockIdx.x * blockDim.x + threadIdx.x;
    const int H4 = HH / 4;
    if (idx >= BB * NSEQ * H4) return;
    int hv = idx % H4;
    int n  = (idx / H4) % NSEQ;
    int b  = idx / (H4 * NSEQ);
    float4 val;
    if (n < EE) {
        val = ((const float4*)vents)[(size_t)(b * EE + n) * H4 + hv];
    } else {
        int r = rels[b * RR + (n - EE)];
        val = ((const float4*)renc)[(size_t)r * H4 + hv];
    }
    ((float4*)g_x)[idx] = val;
}

// ======== generic tf32 tensor-core GEMM core ========
// C[M,N] = A[M,K] @ B[K,N] (+bias)(+prelu)
// Block 128x128, BK=16, 256 threads, warp grid 2(m) x 4(n), warp tile 64x32.
template<int EPI>   // 0: none, 1: +bias, 2: +bias +prelu(alpha per col)
__device__ __forceinline__ void gemm_core(
    const float* __restrict__ A, int lda,
    const float* __restrict__ B, int ldb,
    float* __restrict__ C, int ldc, int K,
    const float* __restrict__ bias,
    const float* __restrict__ alpha,
    int bx, int by)
{
    __shared__ __align__(16) unsigned As[2][8][32][4];   // [k8][mtile][lane][reg]
    __shared__ __align__(16) unsigned Bs[2][16][32][2];  // [k8][ntile][lane][reg]
    const int tid  = threadIdx.x;
    const int lane = tid & 31, wid = tid >> 5;
    const int wm = wid & 1, wn = wid >> 1;
    const float* Ab = A + (size_t)(by * 128) * lda;
    const float* Bb = B + bx * 128;

    float acc[4][4][4];
#pragma unroll
    for (int t = 0; t < 4; t++)
#pragma unroll
        for (int nt = 0; nt < 4; nt++)
#pragma unroll
            for (int r = 0; r < 4; r++) acc[t][nt][r] = 0.f;

    for (int k0 = 0; k0 < K; k0 += 16) {
        // stage A: 128 rows x 16 cols
#pragma unroll
        for (int i = 0; i < 2; i++) {
            int idx = tid + 256 * i;
            int row = idx >> 2, c4 = (idx & 3) << 2;
            float4 v = *(const float4*)(Ab + (size_t)row * lda + k0 + c4);
            int k8  = c4 >> 3;
            int t   = row >> 4;
            int reg = ((row & 15) >> 3) + ((c4 & 7) >> 1);  // + 2*((c4%8)/4)
            int lb  = (row & 7) << 2;
            As[k8][t][lb + 0][reg] = f2tf32(v.x);
            As[k8][t][lb + 1][reg] = f2tf32(v.y);
            As[k8][t][lb + 2][reg] = f2tf32(v.z);
            As[k8][t][lb + 3][reg] = f2tf32(v.w);
        }
        // stage B: 16 rows(k) x 128 cols(n)
#pragma unroll
        for (int i = 0; i < 2; i++) {
            int idx = tid + 256 * i;
            int kk = idx >> 5, n4 = (idx & 31) << 2;
            float4 v = *(const float4*)(Bb + (size_t)(k0 + kk) * ldb + n4);
            int k8  = kk >> 3;
            int nt  = n4 >> 3;
            int reg = (kk & 7) >> 2;
            int lb  = ((n4 & 7) << 2) + (kk & 3);
            Bs[k8][nt][lb     ][reg] = f2tf32(v.x);
            Bs[k8][nt][lb +  4][reg] = f2tf32(v.y);
            Bs[k8][nt][lb +  8][reg] = f2tf32(v.z);
            Bs[k8][nt][lb + 12][reg] = f2tf32(v.w);
        }
        __syncthreads();
#pragma unroll
        for (int s = 0; s < 2; s++) {
            unsigned af[4][4], bf[4][2];
#pragma unroll
            for (int t = 0; t < 4; t++)
                *(uint4*)af[t] = *(const uint4*)As[s][wm * 4 + t][lane];
#pragma unroll
            for (int nt = 0; nt < 4; nt++)
                *(uint2*)bf[nt] = *(const uint2*)Bs[s][wn * 4 + nt][lane];
#pragma unroll
            for (int t = 0; t < 4; t++)
#pragma unroll
                for (int nt = 0; nt < 4; nt++)
                    mma_tf32(acc[t][nt], af[t], bf[nt]);
        }
        __syncthreads();
    }

    // epilogue
    const int r  = lane >> 2;
    const int cq = (lane & 3) << 1;
#pragma unroll
    for (int t = 0; t < 4; t++) {
        int row = by * 128 + wm * 64 + t * 16 + r;
#pragma unroll
        for (int nt = 0; nt < 4; nt++) {
            int col = bx * 128 + wn * 32 + nt * 8 + cq;
            float2 v0 = make_float2(acc[t][nt][0], acc[t][nt][1]);
            float2 v1 = make_float2(acc[t][nt][2], acc[t][nt][3]);
            if (EPI >= 1) {
                float b0 = bias[col], b1 = bias[col + 1];
                v0.x += b0; v0.y += b1; v1.x += b0; v1.y += b1;
            }
            if (EPI == 2) {
                float a0 = alpha[col], a1 = alpha[col + 1];
                v0.x = (v0.x >= 0.f) ? v0.x : a0 * v0.x;
                v0.y = (v0.y >= 0.f) ? v0.y : a1 * v0.y;
                v1.x = (v1.x >= 0.f) ? v1.x : a0 * v1.x;
                v1.y = (v1.y >= 0.f) ? v1.y : a1 * v1.y;
            }
            *(float2*)(C + (size_t)row * ldc + col)       = v0;
            *(float2*)(C + (size_t)(row + 8) * ldc + col) = v1;
        }
    }
}

template<int EPI>
__global__ __launch_bounds__(256)
void k_mma(const float* __restrict__ A, int lda,
           const float* __restrict__ B, int ldb,
           float* __restrict__ C, int ldc, int K,
           const float* __restrict__ bias,
           const float* __restrict__ alpha) {
    gemm_core<EPI>(A, lda, B, ldb, C, ldc, K, bias, alpha, blockIdx.x, blockIdx.y);
}

// AV: per (b,h), C[q, d] = S[q, k] @ V[k, d]
__global__ __launch_bounds__(256)
void k_av_mma() {
    const int z = blockIdx.z, b = z >> 2, h = z & 3;
    gemm_core<0>(g_s + (size_t)z * NSEQ * NSEQ, NSEQ,
                 g_v + (size_t)b * NSEQ * HH + h * DHEAD, HH,
                 g_q + (size_t)b * NSEQ * HH + h * DHEAD, HH, NSEQ,
                 nullptr, nullptr, blockIdx.x, blockIdx.y);
}

// ======== scores: S = (Q K^T)/sqrt(DH), masked by adj ========
__global__ __launch_bounds__(256)
void k_scores_mma(const int* __restrict__ adjs) {
    __shared__ __align__(16) unsigned As[2][8][32][4];    // Q frags
    __shared__ __align__(16) unsigned Bs[2][16][2][32];   // K frags [k8][ntile][reg][lane]
    const int z = blockIdx.z, b = z >> 2, h = z & 3;
    const float* Q  = g_q + (size_t)b * NSEQ * HH + h * DHEAD;
    const float* Kp = g_k + (size_t)b * NSEQ * HH + h * DHEAD;
    const int q0  = blockIdx.y * 128;
    const int k0c = blockIdx.x * 128;
    const int tid  = threadIdx.x;
    const int lane = tid & 31, wid = tid >> 5;
    const int wm = wid & 1, wn = wid >> 1;

    float acc[4][4][4];
#pragma unroll
    for (int t = 0; t < 4; t++)
#pragma unroll
        for (int nt = 0; nt < 4; nt++)
#pragma unroll
            for (int r = 0; r < 4; r++) acc[t][nt][r] = 0.f;

    for (int kc = 0; kc < DHEAD; kc += 16) {
        // stage Q (A operand): rows q0+row, cols kc+c4
#pragma unroll
        for (int i = 0; i < 2; i++) {
            int idx = tid + 256 * i;
            int row = idx >> 2, c4 = (idx & 3) << 2;
            float4 v = *(const float4*)(Q + (size_t)(q0 + row) * HH + kc + c4);
            int k8  = c4 >> 3;
            int t   = row >> 4;
            int reg = ((row & 15) >> 3) + ((c4 & 7) >> 1);
            int lb  = (row & 7) << 2;
            As[k8][t][lb + 0][reg] = f2tf32(v.x);
            As[k8][t][lb + 1][reg] = f2tf32(v.y);
            As[k8][t][lb + 2][reg] = f2tf32(v.z);
            As[k8][t][lb + 3][reg] = f2tf32(v.w);
        }
        // stage K (B operand, d = MMA k-dim): keys k0c+n, cols kc+c4
#pragma unroll
        for (int i = 0; i < 2; i++) {
            int idx = tid + 256 * i;
            int n = idx >> 2, c4 = (idx & 3) << 2;
            float4 v = *(const float4*)(Kp + (size_t)(k0c + n) * HH + kc + c4);
            int k8  = c4 >> 3;
            int nt  = n >> 3;
            int reg = (c4 & 7) >> 2;
            uint4 w = make_uint4(f2tf32(v.x), f2tf32(v.y), f2tf32(v.z), f2tf32(v.w));
            *(uint4*)&Bs[k8][nt][reg][(n & 7) << 2] = w;
        }
        __syncthreads();
#pragma unroll
        for (int s = 0; s < 2; s++) {
            unsigned af[4][4], bf[4][2];
#pragma unroll
            for (int t = 0; t < 4; t++)
                *(uint4*)af[t] = *(const uint4*)As[s][wm * 4 + t][lane];
#pragma unroll
            for (int nt = 0; nt < 4; nt++) {
                bf[nt][0] = Bs[s][wn * 4 + nt][0][lane];
                bf[nt][1] = Bs[s][wn * 4 + nt][1][lane];
            }
#pragma unroll
            for (int t = 0; t < 4; t++)
#pragma unroll
                for (int nt = 0; nt < 4; nt++)
                    mma_tf32(acc[t][nt], af[t], bf[nt]);
        }
        __syncthreads();
    }

    const float rs = 0.08838834764831845f;   // 1/sqrt(128)
    float* S = g_s + (size_t)z * NSEQ * NSEQ;
    const int* adj = adjs + (size_t)b * NSEQ * NSEQ;
    const int r  = lane >> 2;
    const int cq = (lane & 3) << 1;
#pragma unroll
    for (int t = 0; t < 4; t++) {
        int row = q0 + wm * 64 + t * 16 + r;
#pragma unroll
        for (int nt = 0; nt < 4; nt++) {
            int col = k0c + wn * 32 + nt * 8 + cq;
            int2 m0 = *(const int2*)(adj + (size_t)row * NSEQ + col);
            int2 m1 = *(const int2*)(adj + (size_t)(row + 8) * NSEQ + col);
            float2 v0, v1;
            v0.x = m0.x ? acc[t][nt][0] * rs : -1e9f;
            v0.y = m0.y ? acc[t][nt][1] * rs : -1e9f;
            v1.x = m1.x ? acc[t][nt][2] * rs : -1e9f;
            v1.y = m1.y ? acc[t][nt][3] * rs : -1e9f;
            *(float2*)(S + (size_t)row * NSEQ + col)       = v0;
            *(float2*)(S + (size_t)(row + 8) * NSEQ + col) = v1;
        }
    }
}

// -------- softmax over rows of g_s (register-resident, 1R + 1W) --------
__global__ __launch_bounds__(256)
void k_softmax() {
    float* p = g_s + (size_t)blockIdx.x * NSEQ;
    const int tid = threadIdx.x;
    float4 v0 = ((const float4*)p)[tid];
    float4 v1 = ((const float4*)p)[tid + 256];
    float m = fmaxf(fmaxf(fmaxf(v0.x, v0.y), fmaxf(v0.z, v0.w)),
                    fmaxf(fmaxf(v1.x, v1.y), fmaxf(v1.z, v1.w)));
    __shared__ float red[8];
#pragma unroll
    for (int o = 16; o; o >>= 1) m = fmaxf(m, __shfl_xor_sync(~0u, m, o));
    if ((tid & 31) == 0) red[tid >> 5] = m;
    __syncthreads();
    float mAll = red[0];
#pragma unroll
    for (int i = 1; i < 8; i++) mAll = fmaxf(mAll, red[i]);

    v0.x = expf(v0.x - mAll); v0.y = expf(v0.y - mAll);
    v0.z = expf(v0.z - mAll); v0.w = expf(v0.w - mAll);
    v1.x = expf(v1.x - mAll); v1.y = expf(v1.y - mAll);
    v1.z = expf(v1.z - mAll); v1.w = expf(v1.w - mAll);
    float s = v0.x + v0.y + v0.z + v0.w + v1.x + v1.y + v1.z + v1.w;
    __syncthreads();
#pragma unroll
    for (int o = 16; o; o >>= 1) s += __shfl_xor_sync(~0u, s, o);
    if ((tid & 31) == 0) red[tid >> 5] = s;
    __syncthreads();
    float sAll = red[0];
#pragma unroll
    for (int i = 1; i < 8; i++) sAll += red[i];
    float inv = 1.f / sAll;

    v0.x *= inv; v0.y *= inv; v0.z *= inv; v0.w *= inv;
    v1.x *= inv; v1.y *= inv; v1.z *= inv; v1.w *= inv;
    ((float4*)p)[tid]       = v0;
    ((float4*)p)[tid + 256] = v1;
}

// -------- layernorm (optional residual add), warp per row --------
__global__ __launch_bounds__(256)
void k_ln(const float* __restrict__ X, const float* __restrict__ Rres,
          const float* __restrict__ g, const float* __restrict__ bsh,
          float* __restrict__ out) {
    const int row  = blockIdx.x * 8 + (threadIdx.x >> 5);
    const int lane = threadIdx.x & 31;
    const float4* xr = (const float4*)(X + (size_t)row * HH);
    float4 v[4];
    float sum = 0.f, sq = 0.f;
#pragma unroll
    for (int i = 0; i < 4; i++) {
        float4 a = xr[lane + 32 * i];
        if (Rres) {
            float4 r = ((const float4*)(Rres + (size_t)row * HH))[lane + 32 * i];
            a.x += r.x; a.y += r.y; a.z += r.z; a.w += r.w;
        }
        v[i] = a;
        sum += a.x + a.y + a.z + a.w;
        sq  += a.x * a.x + a.y * a.y + a.z * a.z + a.w * a.w;
    }
#pragma unroll
    for (int o = 16; o; o >>= 1) {
        sum += __shfl_xor_sync(~0u, sum, o);
        sq  += __shfl_xor_sync(~0u, sq,  o);
    }
    const float mu   = sum * (1.f / HH);
    const float var  = sq * (1.f / HH) - mu * mu;
    const float rstd = rsqrtf(var + 1e-5f);
    float4* op = (float4*)(out + (size_t)row * HH);
#pragma unroll
    for (int i = 0; i < 4; i++) {
        int c4 = lane + 32 * i;
        float4 gg = ((const float4*)g)[c4];
        float4 bb = ((const float4*)bsh)[c4];
        float4 a = v[i];
        a.x = (a.x - mu) * rstd * gg.x + bb.x;
        a.y = (a.y - mu) * rstd * gg.y + bb.y;
        a.z = (a.z - mu) * rstd * gg.z + bb.z;
        a.w = (a.w - mu) * rstd * gg.w + bb.w;
        op[c4] = a;
    }
}

// -------- output assembly: [glob | gents | emask] --------
__global__ void k_out(float* __restrict__ out) {
    const size_t GENTS = (size_t)BB * NSEQ * HH;
    size_t i = (size_t)blockIdx.x * 256 + threadIdx.x;
    if (i < (size_t)BB * HH) {
        size_t b = i / HH, hc = i % HH;
        out[i] = g_x[b * NSEQ * HH + (size_t)EE * HH + hc];
    }
    if (i < GENTS) out[(size_t)BB * HH + i] = g_x[i];
    if (i < (size_t)BB * NSEQ) out[(size_t)BB * HH + GENTS + i] = 1.0f;
}

extern "C" void kernel_launch(void* const* d_in, const int* in_sizes, int n_in,
                              void* d_out, int out_size) {
    int s = (n_in >= 22) ? 1 : 0;
    const int*   adjs  = (const int*)d_in[0];
    const int*   rels  = (const int*)d_in[1];
    const float* vents = (const float*)d_in[2];
    const float* renc  = (const float*)d_in[3 + s];
    const float* Wq = (const float*)d_in[4 + s];
    const float* Wk = (const float*)d_in[5 + s];
    const float* Wv = (const float*)d_in[6 + s];
    const float* Wo = (const float*)d_in[7 + s];
    const float* W1 = (const float*)d_in[8 + s];
    const float* W2 = (const float*)d_in[9 + s];
    const float* bq = (const float*)d_in[10 + s];
    const float* bk = (const float*)d_in[11 + s];
    const float* bv = (const float*)d_in[12 + s];
    const float* bo = (const float*)d_in[13 + s];
    const float* b1 = (const float*)d_in[14 + s];
    const float* b2 = (const float*)d_in[15 + s];
    const float* ln1g = (const float*)d_in[16 + s];
    const float* ln1b = (const float*)d_in[17 + s];
    const float* ln2g = (const float*)d_in[18 + s];
    const float* ln2b = (const float*)d_in[19 + s];
    const float* pa   = (const float*)d_in[20 + s];

    float *px, *pq, *pk, *pv, *pt, *pf;
    cudaGetSymbolAddress((void**)&px, g_x);
    cudaGetSymbolAddress((void**)&pq, g_q);
    cudaGetSymbolAddress((void**)&pk, g_k);
    cudaGetSymbolAddress((void**)&pv, g_v);
    cudaGetSymbolAddress((void**)&pt, g_t);
    cudaGetSymbolAddress((void**)&pf, g_f);

    k_build_x<<<(BB * NSEQ * (HH / 4) + 255) / 256, 256>>>(vents, renc, rels);

    for (int j = 0; j < PP; j++) {
        const float* Wqj = Wq + (size_t)j * HH * HH;
        const float* Wkj = Wk + (size_t)j * HH * HH;
        const float* Wvj = Wv + (size_t)j * HH * HH;
        const float* Woj = Wo + (size_t)j * HH * HH;
        const float* W1j = W1 + (size_t)j * HH * FFD;
        const float* W2j = W2 + (size_t)j * FFD * HH;

        dim3 gp(HH / 128, MTOK / 128);          // (4, 64)
        k_mma<1><<<gp, 256>>>(px, HH, Wqj, HH, pq, HH, HH, bq + j * HH, nullptr);
        k_mma<1><<<gp, 256>>>(px, HH, Wkj, HH, pk, HH, HH, bk + j * HH, nullptr);
        k_mma<1><<<gp, 256>>>(px, HH, Wvj, HH, pv, HH, HH, bv + j * HH, nullptr);

        dim3 gs(NSEQ / 128, NSEQ / 128, BB * NHEAD);
        k_scores_mma<<<gs, 256>>>(adjs);
        k_softmax<<<BB * NHEAD * NSEQ, 256>>>();
        dim3 ga(1, NSEQ / 128, BB * NHEAD);
        k_av_mma<<<ga, 256>>>();                 // o -> g_q

        k_mma<1><<<gp, 256>>>(pq, HH, Woj, HH, pk, HH, HH, bo + j * HH, nullptr);
        k_ln<<<MTOK / 8, 256>>>(pk, nullptr, ln1g + j * HH, ln1b + j * HH, pt);

        dim3 g1(FFD / 128, MTOK / 128);
        k_mma<2><<<g1, 256>>>(pt, HH, W1j, FFD, pf, FFD, HH, b1 + j * FFD, pa + j * FFD);
        dim3 g2(HH / 128, MTOK / 128);
        k_mma<1><<<g2, 256>>>(pf, FFD, W2j, HH, pk, HH, FFD, b2 + j * HH, nullptr);

        k_ln<<<MTOK / 8, 256>>>(pk, pt, ln2g + j * HH, ln2b + j * HH, px);
    }

    k_out<<<(BB * NSEQ * HH + 255) / 256, 256>>>((float*)d_out);
}

// round 4
// speedup vs baseline: 3.0267x; 2.8251x over previous
#include <cuda_runtime.h>
#include <cstdint>

// Problem constants
#define BB     4
#define NSEQ   2048
#define EE     1600
#define RR     448
#define HH     512
#define NHEAD  4
#define DHEAD  128
#define PP     2
#define FFD    2048
#define MTOK   (BB*NSEQ)

// -------- scratch (device globals; no allocation allowed) --------
__device__ float g_x[(size_t)BB*NSEQ*HH];
__device__ float g_q[(size_t)BB*NSEQ*HH];
__device__ float g_k[(size_t)BB*NSEQ*HH];
__device__ float g_v[(size_t)BB*NSEQ*HH];
__device__ float g_t[(size_t)BB*NSEQ*HH];
__device__ float g_f[(size_t)BB*NSEQ*FFD];
__device__ float g_s[(size_t)BB*NHEAD*NSEQ*NSEQ];     // scores
__device__ float g_wt[(size_t)PP*3145728];            // transposed weights
__device__ float g_vt[(size_t)BB*NHEAD*DHEAD*NSEQ];   // transposed V

// ---------------- helpers ----------------
__device__ __forceinline__ unsigned f2tf32(float x) {
    unsigned r; asm("cvt.rna.tf32.f32 %0, %1;" : "=r"(r) : "f"(x)); return r;
}
__device__ __forceinline__ float rnd32(float x) {
    return __uint_as_float(f2tf32(x));
}
__device__ __forceinline__ uint32_t smem_u32(const void* p) {
    uint32_t a;
    asm("{ .reg .u64 t; cvta.to.shared.u64 t, %1; cvt.u32.u64 %0, t; }" : "=r"(a) : "l"(p));
    return a;
}
__device__ __forceinline__ unsigned lds32(uint32_t a) {
    unsigned v; asm("ld.shared.b32 %0, [%1];" : "=r"(v) : "r"(a)); return v;
}
#define SWZ128(o) ((o) ^ (((o) >> 3) & 0x70))

__device__ __forceinline__ void mma_tf32(float* d, const unsigned* a, const unsigned* b) {
    asm volatile("mma.sync.aligned.m16n8k8.row.col.f32.tf32.tf32.f32 "
                 "{%0,%1,%2,%3}, {%4,%5,%6,%7}, {%8,%9}, {%0,%1,%2,%3};"
                 : "+f"(d[0]), "+f"(d[1]), "+f"(d[2]), "+f"(d[3])
                 : "r"(a[0]), "r"(a[1]), "r"(a[2]), "r"(a[3]),
                   "r"(b[0]), "r"(b[1]));
}

#define CP16(d, s)   asm volatile("cp.async.cg.shared.global [%0], [%1], 16;" :: "r"(d), "l"(s))
#define CP_COMMIT()  asm volatile("cp.async.commit_group;")
#define CP_WAIT(n)   asm volatile("cp.async.wait_group %0;" :: "n"(n))

#define STAGE_SZ   32768     // A(16KB, 128x32 f32 SW128) + B(16KB)
#define SMEM_DYN   (2*STAGE_SZ)

// ======== pipelined tf32 mma.sync GEMM core ========
// C[M,N] tile (128x128) at (bx,by): C = A[M,K] @ B^T, B stored [N,K] K-major.
// 256 threads, warp grid 2(m) x 4(n), warp tile 64x32, BK=32, 2-stage cp.async.
// EPI: 0 none, 1 +bias, 2 +bias+prelu, 3 scores (scale+mask)
template<int EPI>
__device__ __forceinline__ void mm_core(
    const float* __restrict__ A, int lda,
    const float* __restrict__ B, int ldb,
    float* __restrict__ C, int ldc, int K,
    const float* __restrict__ bias,
    const float* __restrict__ alpha,
    const int* __restrict__ adj)
{
    extern __shared__ __align__(1024) char dynsmem[];
    const uint32_t sb = smem_u32(dynsmem);
    const int tid = threadIdx.x, lane = tid & 31, wid = tid >> 5;
    const int wm = wid & 1, wn = wid >> 1;
    const int row0 = blockIdx.y * 128, col0 = blockIdx.x * 128;

    // stage k-tile 'it' (A 128x32, B 128x32, both 128B rows, SW128)
    auto copy_tile = [&](int it, int s) {
        const uint32_t a_s = sb + s * STAGE_SZ;
        const uint32_t b_s = a_s + 16384;
        const int k0 = it << 5;
#pragma unroll
        for (int u = 0; u < 4; u++) {
            int idx = tid + 256 * u;            // 0..1023
            int r = idx >> 3, c16 = (idx & 7) << 4;
            uint32_t sw = SWZ128((r << 7) + c16);
            CP16(a_s + sw, A + (size_t)(row0 + r) * lda + k0 + (c16 >> 2));
            CP16(b_s + sw, B + (size_t)(col0 + r) * ldb + k0 + (c16 >> 2));
        }
    };

    float acc[4][4][4];
#pragma unroll
    for (int t = 0; t < 4; t++)
#pragma unroll
        for (int nt = 0; nt < 4; nt++)
#pragma unroll
            for (int r = 0; r < 4; r++) acc[t][nt][r] = 0.f;

    const int T = K >> 5;
    copy_tile(0, 0);
    CP_COMMIT();

    for (int it = 0; it < T; it++) {
        const int s = it & 1;
        if (it + 1 < T) {
            copy_tile(it + 1, s ^ 1);
            CP_COMMIT();
            CP_WAIT(1);
        } else {
            CP_WAIT(0);
        }
        __syncthreads();

        const uint32_t a_s = sb + s * STAGE_SZ;
        const uint32_t b_s = a_s + 16384;
        const int fr = lane >> 2, fc = lane & 3;
#pragma unroll
        for (int k8 = 0; k8 < 4; k8++) {
            const int kb = k8 << 3;
            unsigned af[4][4], bf[4][2];
#pragma unroll
            for (int t = 0; t < 4; t++) {
                const int r = wm * 64 + t * 16 + fr;
                const int c = kb + fc;
                af[t][0] = lds32(a_s + SWZ128((r << 7) + (c << 2)));
                af[t][1] = lds32(a_s + SWZ128(((r + 8) << 7) + (c << 2)));
                af[t][2] = lds32(a_s + SWZ128((r << 7) + ((c + 4) << 2)));
                af[t][3] = lds32(a_s + SWZ128(((r + 8) << 7) + ((c + 4) << 2)));
            }
#pragma unroll
            for (int nt = 0; nt < 4; nt++) {
                const int n = wn * 32 + nt * 8 + fr;
                const int c = kb + fc;
                bf[nt][0] = lds32(b_s + SWZ128((n << 7) + (c << 2)));
                bf[nt][1] = lds32(b_s + SWZ128((n << 7) + ((c + 4) << 2)));
            }
#pragma unroll
            for (int t = 0; t < 4; t++)
#pragma unroll
                for (int nt = 0; nt < 4; nt++)
                    mma_tf32(acc[t][nt], af[t], bf[nt]);
        }
        __syncthreads();
    }

    // epilogue (register-direct, tf32-rounded outputs)
    const float rs = 0.08838834764831845f;   // 1/sqrt(128)
    const int r = lane >> 2;
    const int cq = (lane & 3) << 1;
#pragma unroll
    for (int t = 0; t < 4; t++) {
        const int row = row0 + wm * 64 + t * 16 + r;
#pragma unroll
        for (int nt = 0; nt < 4; nt++) {
            const int col = col0 + wn * 32 + nt * 8 + cq;
            float2 v0 = make_float2(acc[t][nt][0], acc[t][nt][1]);
            float2 v1 = make_float2(acc[t][nt][2], acc[t][nt][3]);
            if (EPI == 1 || EPI == 2) {
                float b0 = bias[col], b1 = bias[col + 1];
                v0.x += b0; v0.y += b1; v1.x += b0; v1.y += b1;
            }
            if (EPI == 2) {
                float a0 = alpha[col], a1 = alpha[col + 1];
                v0.x = (v0.x >= 0.f) ? v0.x : a0 * v0.x;
                v0.y = (v0.y >= 0.f) ? v0.y : a1 * v0.y;
                v1.x = (v1.x >= 0.f) ? v1.x : a0 * v1.x;
                v1.y = (v1.y >= 0.f) ? v1.y : a1 * v1.y;
            }
            if (EPI == 3) {
                int2 m0 = *(const int2*)(adj + (size_t)row * NSEQ + col);
                int2 m1 = *(const int2*)(adj + (size_t)(row + 8) * NSEQ + col);
                v0.x = m0.x ? v0.x * rs : -1e9f;
                v0.y = m0.y ? v0.y * rs : -1e9f;
                v1.x = m1.x ? v1.x * rs : -1e9f;
                v1.y = m1.y ? v1.y * rs : -1e9f;
            }
            v0.x = rnd32(v0.x); v0.y = rnd32(v0.y);
            v1.x = rnd32(v1.x); v1.y = rnd32(v1.y);
            *(float2*)(C + (size_t)row * ldc + col)       = v0;
            *(float2*)(C + (size_t)(row + 8) * ldc + col) = v1;
        }
    }
}

template<int EPI>
__global__ __launch_bounds__(256)
void k_mm(const float* __restrict__ A, int lda,
          const float* __restrict__ B, int ldb,
          float* __restrict__ C, int ldc, int K,
          const float* __restrict__ bias,
          const float* __restrict__ alpha) {
    mm_core<EPI>(A, lda, B, ldb, C, ldc, K, bias, alpha, nullptr);
}

__global__ __launch_bounds__(256)
void k_sc(const int* __restrict__ adjs) {
    const int z = blockIdx.z, b = z >> 2, h = z & 3;
    mm_core<3>(g_q + (size_t)b * NSEQ * HH + h * DHEAD, HH,
               g_k + (size_t)b * NSEQ * HH + h * DHEAD, HH,
               g_s + (size_t)z * NSEQ * NSEQ, NSEQ, DHEAD,
               nullptr, nullptr, adjs + (size_t)b * NSEQ * NSEQ);
}

__global__ __launch_bounds__(256)
void k_av() {
    const int z = blockIdx.z, b = z >> 2, h = z & 3;
    mm_core<0>(g_s + (size_t)z * NSEQ * NSEQ, NSEQ,
               g_vt + (size_t)z * DHEAD * NSEQ, NSEQ,
               g_q + (size_t)b * NSEQ * HH + h * DHEAD, HH, NSEQ,
               nullptr, nullptr, nullptr);
}

// -------- transpose (32x32 tiles, rounds to tf32): dst[c][r] = src[r][c] --------
__global__ void k_tr(const float* __restrict__ src, float* __restrict__ dst,
                     int ss, int ds) {
    __shared__ float t[32][33];
    const int c0 = blockIdx.x * 32, r0 = blockIdx.y * 32;
    const int tx = threadIdx.x, ty = threadIdx.y;
#pragma unroll
    for (int i = 0; i < 4; i++)
        t[ty + 8 * i][tx] = src[(size_t)(r0 + ty + 8 * i) * ss + c0 + tx];
    __syncthreads();
#pragma unroll
    for (int i = 0; i < 4; i++)
        dst[(size_t)(c0 + ty + 8 * i) * ds + r0 + tx] = rnd32(t[tx][ty + 8 * i]);
}

// V transpose: per z=(b,h): g_v[b][seq][h*128+d] -> g_vt[z][d][seq]
__global__ void k_tr_v() {
    __shared__ float t[32][33];
    const int z = blockIdx.z, b = z >> 2, h = z & 3;
    const float* src = g_v + (size_t)b * NSEQ * HH + h * DHEAD;
    float* dst = g_vt + (size_t)z * DHEAD * NSEQ;
    const int c0 = blockIdx.x * 32, r0 = blockIdx.y * 32;
    const int tx = threadIdx.x, ty = threadIdx.y;
#pragma unroll
    for (int i = 0; i < 4; i++)
        t[ty + 8 * i][tx] = src[(size_t)(r0 + ty + 8 * i) * HH + c0 + tx];
    __syncthreads();
#pragma unroll
    for (int i = 0; i < 4; i++)
        dst[(size_t)(c0 + ty + 8 * i) * NSEQ + r0 + tx] = rnd32(t[tx][ty + 8 * i]);
}

// -------- build x = concat(vents, renc_w[rels]) (tf32-rounded) --------
__global__ void k_build_x(const float* __restrict__ vents,
                          const float* __restrict__ renc,
                          const int*   __restrict__ rels) {
    int idx = blockIdx.x * blockDim.x + threadIdx.x;
    const int H4 = HH / 4;
    if (idx >= BB * NSEQ * H4) return;
    int hv = idx % H4;
    int n  = (idx / H4) % NSEQ;
    int b  = idx / (H4 * NSEQ);
    float4 val;
    if (n < EE) {
        val = ((const float4*)vents)[(size_t)(b * EE + n) * H4 + hv];
    } else {
        int r = rels[b * RR + (n - EE)];
        val = ((const float4*)renc)[(size_t)r * H4 + hv];
    }
    val.x = rnd32(val.x); val.y = rnd32(val.y);
    val.z = rnd32(val.z); val.w = rnd32(val.w);
    ((float4*)g_x)[idx] = val;
}

// -------- softmax over rows of g_s (tf32-rounded outputs) --------
__global__ __launch_bounds__(256)
void k_softmax() {
    float* p = g_s + (size_t)blockIdx.x * NSEQ;
    const int tid = threadIdx.x;
    float4 v0 = ((const float4*)p)[tid];
    float4 v1 = ((const float4*)p)[tid + 256];
    float m = fmaxf(fmaxf(fmaxf(v0.x, v0.y), fmaxf(v0.z, v0.w)),
                    fmaxf(fmaxf(v1.x, v1.y), fmaxf(v1.z, v1.w)));
    __shared__ float red[8];
#pragma unroll
    for (int o = 16; o; o >>= 1) m = fmaxf(m, __shfl_xor_sync(~0u, m, o));
    if ((tid & 31) == 0) red[tid >> 5] = m;
    __syncthreads();
    float mAll = red[0];
#pragma unroll
    for (int i = 1; i < 8; i++) mAll = fmaxf(mAll, red[i]);

    v0.x = expf(v0.x - mAll); v0.y = expf(v0.y - mAll);
    v0.z = expf(v0.z - mAll); v0.w = expf(v0.w - mAll);
    v1.x = expf(v1.x - mAll); v1.y = expf(v1.y - mAll);
    v1.z = expf(v1.z - mAll); v1.w = expf(v1.w - mAll);
    float s = v0.x + v0.y + v0.z + v0.w + v1.x + v1.y + v1.z + v1.w;
    __syncthreads();
#pragma unroll
    for (int o = 16; o; o >>= 1) s += __shfl_xor_sync(~0u, s, o);
    if ((tid & 31) == 0) red[tid >> 5] = s;
    __syncthreads();
    float sAll = red[0];
#pragma unroll
    for (int i = 1; i < 8; i++) sAll += red[i];
    float inv = 1.f / sAll;

    v0.x = rnd32(v0.x * inv); v0.y = rnd32(v0.y * inv);
    v0.z = rnd32(v0.z * inv); v0.w = rnd32(v0.w * inv);
    v1.x = rnd32(v1.x * inv); v1.y = rnd32(v1.y * inv);
    v1.z = rnd32(v1.z * inv); v1.w = rnd32(v1.w * inv);
    ((float4*)p)[tid]       = v0;
    ((float4*)p)[tid + 256] = v1;
}

// -------- layernorm (optional residual), warp per row, tf32-rounded out --------
__global__ __launch_bounds__(256)
void k_ln(const float* __restrict__ X, const float* __restrict__ Rres,
          const float* __restrict__ g, const float* __restrict__ bsh,
          float* __restrict__ out) {
    const int row  = blockIdx.x * 8 + (threadIdx.x >> 5);
    const int lane = threadIdx.x & 31;
    const float4* xr = (const float4*)(X + (size_t)row * HH);
    float4 v[4];
    float sum = 0.f, sq = 0.f;
#pragma unroll
    for (int i = 0; i < 4; i++) {
        float4 a = xr[lane + 32 * i];
        if (Rres) {
            float4 r = ((const float4*)(Rres + (size_t)row * HH))[lane + 32 * i];
            a.x += r.x; a.y += r.y; a.z += r.z; a.w += r.w;
        }
        v[i] = a;
        sum += a.x + a.y + a.z + a.w;
        sq  += a.x * a.x + a.y * a.y + a.z * a.z + a.w * a.w;
    }
#pragma unroll
    for (int o = 16; o; o >>= 1) {
        sum += __shfl_xor_sync(~0u, sum, o);
        sq  += __shfl_xor_sync(~0u, sq,  o);
    }
    const float mu   = sum * (1.f / HH);
    const float var  = sq * (1.f / HH) - mu * mu;
    const float rstd = rsqrtf(var + 1e-5f);
    float4* op = (float4*)(out + (size_t)row * HH);
#pragma unroll
    for (int i = 0; i < 4; i++) {
        int c4 = lane + 32 * i;
        float4 gg = ((const float4*)g)[c4];
        float4 bb = ((const float4*)bsh)[c4];
        float4 a = v[i];
        a.x = rnd32((a.x - mu) * rstd * gg.x + bb.x);
        a.y = rnd32((a.y - mu) * rstd * gg.y + bb.y);
        a.z = rnd32((a.z - mu) * rstd * gg.z + bb.z);
        a.w = rnd32((a.w - mu) * rstd * gg.w + bb.w);
        op[c4] = a;
    }
}

// -------- output assembly: [glob | gents | emask] --------
__global__ void k_out(float* __restrict__ out) {
    const size_t GENTS = (size_t)BB * NSEQ * HH;
    size_t i = (size_t)blockIdx.x * 256 + threadIdx.x;
    if (i < (size_t)BB * HH) {
        size_t b = i / HH, hc = i % HH;
        out[i] = g_x[b * NSEQ * HH + (size_t)EE * HH + hc];
    }
    if (i < GENTS) out[(size_t)BB * HH + i] = g_x[i];
    if (i < (size_t)BB * NSEQ) out[(size_t)BB * HH + GENTS + i] = 1.0f;
}

extern "C" void kernel_launch(void* const* d_in, const int* in_sizes, int n_in,
                              void* d_out, int out_size) {
    int s = (n_in >= 22) ? 1 : 0;
    const int*   adjs  = (const int*)d_in[0];
    const int*   rels  = (const int*)d_in[1];
    const float* vents = (const float*)d_in[2];
    const float* renc  = (const float*)d_in[3 + s];
    const float* Wq = (const float*)d_in[4 + s];
    const float* Wk = (const float*)d_in[5 + s];
    const float* Wv = (const float*)d_in[6 + s];
    const float* Wo = (const float*)d_in[7 + s];
    const float* W1 = (const float*)d_in[8 + s];
    const float* W2 = (const float*)d_in[9 + s];
    const float* bq = (const float*)d_in[10 + s];
    const float* bk = (const float*)d_in[11 + s];
    const float* bv = (const float*)d_in[12 + s];
    const float* bo = (const float*)d_in[13 + s];
    const float* b1 = (const float*)d_in[14 + s];
    const float* b2 = (const float*)d_in[15 + s];
    const float* ln1g = (const float*)d_in[16 + s];
    const float* ln1b = (const float*)d_in[17 + s];
    const float* ln2g = (const float*)d_in[18 + s];
    const float* ln2b = (const float*)d_in[19 + s];
    const float* pa   = (const float*)d_in[20 + s];

    float *px, *pq, *pk, *pv, *pt, *pf, *pwt;
    cudaGetSymbolAddress((void**)&px, g_x);
    cudaGetSymbolAddress((void**)&pq, g_q);
    cudaGetSymbolAddress((void**)&pk, g_k);
    cudaGetSymbolAddress((void**)&pv, g_v);
    cudaGetSymbolAddress((void**)&pt, g_t);
    cudaGetSymbolAddress((void**)&pf, g_f);
    cudaGetSymbolAddress((void**)&pwt, g_wt);

    cudaFuncSetAttribute(k_mm<0>, cudaFuncAttributeMaxDynamicSharedMemorySize, SMEM_DYN);
    cudaFuncSetAttribute(k_mm<1>, cudaFuncAttributeMaxDynamicSharedMemorySize, SMEM_DYN);
    cudaFuncSetAttribute(k_mm<2>, cudaFuncAttributeMaxDynamicSharedMemorySize, SMEM_DYN);
    cudaFuncSetAttribute(k_sc,   cudaFuncAttributeMaxDynamicSharedMemorySize, SMEM_DYN);
    cudaFuncSetAttribute(k_av,   cudaFuncAttributeMaxDynamicSharedMemorySize, SMEM_DYN);

    k_build_x<<<(BB * NSEQ * (HH / 4) + 255) / 256, 256>>>(vents, renc, rels);

    // transpose all weights to [N,K] K-major (once)
    const size_t LSTR = 3145728;
    dim3 tb(32, 8);
    for (int j = 0; j < PP; j++) {
        float* base = pwt + j * LSTR;
        k_tr<<<dim3(16, 16), tb>>>(Wq + (size_t)j * HH * HH, base + 0,       HH, HH);
        k_tr<<<dim3(16, 16), tb>>>(Wk + (size_t)j * HH * HH, base + 262144,  HH, HH);
        k_tr<<<dim3(16, 16), tb>>>(Wv + (size_t)j * HH * HH, base + 524288,  HH, HH);
        k_tr<<<dim3(16, 16), tb>>>(Wo + (size_t)j * HH * HH, base + 786432,  HH, HH);
        k_tr<<<dim3(64, 16), tb>>>(W1 + (size_t)j * HH * FFD, base + 1048576, FFD, HH);
        k_tr<<<dim3(16, 64), tb>>>(W2 + (size_t)j * FFD * HH, base + 2097152, HH, FFD);
    }

    for (int j = 0; j < PP; j++) {
        float* base = pwt + j * LSTR;
        dim3 gp(HH / 128, MTOK / 128);          // (4, 64)
        k_mm<1><<<gp, 256, SMEM_DYN>>>(px, HH, base + 0,      HH, pq, HH, HH, bq + j * HH, nullptr);
        k_mm<1><<<gp, 256, SMEM_DYN>>>(px, HH, base + 262144, HH, pk, HH, HH, bk + j * HH, nullptr);
        k_mm<1><<<gp, 256, SMEM_DYN>>>(px, HH, base + 524288, HH, pv, HH, HH, bv + j * HH, nullptr);

        k_tr_v<<<dim3(4, 64, 16), tb>>>();

        k_sc<<<dim3(16, 16, 16), 256, SMEM_DYN>>>(adjs);
        k_softmax<<<BB * NHEAD * NSEQ, 256>>>();
        k_av<<<dim3(1, 16, 16), 256, SMEM_DYN>>>();   // attn out -> g_q

        k_mm<1><<<gp, 256, SMEM_DYN>>>(pq, HH, base + 786432, HH, pk, HH, HH, bo + j * HH, nullptr);
        k_ln<<<MTOK / 8, 256>>>(pk, nullptr, ln1g + j * HH, ln1b + j * HH, pt);

        k_mm<2><<<dim3(FFD / 128, MTOK / 128), 256, SMEM_DYN>>>(
            pt, HH, base + 1048576, HH, pf, FFD, HH, b1 + j * FFD, pa + j * FFD);
        k_mm<1><<<dim3(HH / 128, MTOK / 128), 256, SMEM_DYN>>>(
            pf, FFD, base + 2097152, FFD, pk, HH, FFD, b2 + j * HH, nullptr);

        k_ln<<<MTOK / 8, 256>>>(pk, pt, ln2g + j * HH, ln2b + j * HH, px);
    }

    k_out<<<(BB * NSEQ * HH + 255) / 256, 256>>>((float*)d_out);
}